// round 4
// baseline (speedup 1.0000x reference)
#include <cuda_runtime.h>
#include <cstdint>

typedef unsigned long long u64;

#define NN 4096
#define DD 128
#define BM 128
#define BN 128
#define LDAA 264                  // A tile (value-duplicated) row stride in floats
#define LDB  132                  // B tile row stride in floats
#define SMEM_BYTES ((DD * LDAA + DD * LDB) * 4)   // 135168 + 67584 = 202752 B
#define LOG_MIN (-34.538776394910684f)            // log(1e-15)

// ---------------- device scratch (no allocations allowed) ----------------
__device__ float g_neg[32 * NN];   // per (col-block, row) partial negative_sum
__device__ float g_S[32 * NN];     // per (col-block, row) partial sum_pos log(simi)
__device__ float g_P[32 * NN];     // per (col-block, row) partial pos count
__device__ float g_loss;
__device__ unsigned g_maxd, g_maxe, g_mine;

// order-preserving float<->uint encoding for atomicMax/Min
__device__ __forceinline__ unsigned fenc(float f) {
    unsigned u = __float_as_uint(f);
    return (u & 0x80000000u) ? ~u : (u | 0x80000000u);
}
__device__ __forceinline__ float fdec(unsigned u) {
    return (u & 0x80000000u) ? __uint_as_float(u ^ 0x80000000u)
                             : __uint_as_float(~u);
}

// packed f32x2 FMA (SASS FFMA2; bit-identical rounding to 2x fmaf)
__device__ __forceinline__ u64 fma2(u64 a, u64 b, u64 c) {
    u64 d;
    asm("fma.rn.f32x2 %0, %1, %2, %3;" : "=l"(d) : "l"(a), "l"(b), "l"(c));
    return d;
}
__device__ __forceinline__ void unpack2(float& lo, float& hi, u64 v) {
    asm("mov.b64 {%0, %1}, %2;" : "=f"(lo), "=f"(hi) : "l"(v));
}

__global__ void init_kernel() {
    g_maxd = 0u;            // encodes very negative
    g_maxe = 0u;
    g_mine = 0xFFFFFFFFu;   // encodes very positive
}

// ---------------- fused Minkowski-Gram + epilogue ----------------
extern __shared__ float smem[];

__global__ void __launch_bounds__(256, 1)
dist_kernel(const float* __restrict__ x, const int* __restrict__ adj,
            float* __restrict__ dist_out) {
    float* As = smem;               // [DD][LDAA] k-major, DUPLICATED pairs (a,a)
    float* Bs = smem + DD * LDAA;   // [DD][LDB]  k-major

    const int tid = threadIdx.x;
    const int i0 = blockIdx.y * BM;
    const int j0 = blockIdx.x * BN;
    const int tx = tid & 15;
    const int ty = tid >> 4;

    // ---- prefetch adj for this thread's 8x8 sub-tile, pack to 64-bit mask ----
    // Issued before the mainloop so DRAM latency drains under the FFMA loop.
    u64 amask = 0ull;
#pragma unroll
    for (int u = 0; u < 8; u++) {
        const int* arow = adj + (size_t)(i0 + ty * 8 + u) * NN + j0 + tx * 8;
        const int4 av0 = __ldg((const int4*)arow);
        const int4 av1 = __ldg((const int4*)(arow + 4));
        u64 m = 0ull;
        m |= (u64)(av0.x != 0) << 0; m |= (u64)(av0.y != 0) << 1;
        m |= (u64)(av0.z != 0) << 2; m |= (u64)(av0.w != 0) << 3;
        m |= (u64)(av1.x != 0) << 4; m |= (u64)(av1.y != 0) << 5;
        m |= (u64)(av1.z != 0) << 6; m |= (u64)(av1.w != 0) << 7;
        amask |= m << (u * 8);
    }

    // ---- load x tiles to smem, transposed to k-major; A duplicated ----
    {
        const int m = tid >> 1;        // 0..127
        const int half = tid & 1;      // 0..1
        const float4* pa = (const float4*)(x + (size_t)(i0 + m) * DD + half * 64);
        const float4* pb = (const float4*)(x + (size_t)(j0 + m) * DD + half * 64);
#pragma unroll
        for (int t = 0; t < 16; t++) {
            float4 va = pa[t];
            float4 vb = pb[t];
            const int k = half * 64 + t * 4;
            if (k == 0) va.x = -va.x;  // Minkowski signature on A side
            As[(k + 0) * LDAA + 2 * m]     = va.x;
            As[(k + 0) * LDAA + 2 * m + 1] = va.x;
            As[(k + 1) * LDAA + 2 * m]     = va.y;
            As[(k + 1) * LDAA + 2 * m + 1] = va.y;
            As[(k + 2) * LDAA + 2 * m]     = va.z;
            As[(k + 2) * LDAA + 2 * m + 1] = va.z;
            As[(k + 3) * LDAA + 2 * m]     = va.w;
            As[(k + 3) * LDAA + 2 * m + 1] = va.w;
            Bs[(k + 0) * LDB + m] = vb.x;
            Bs[(k + 1) * LDB + m] = vb.y;
            Bs[(k + 2) * LDB + m] = vb.z;
            Bs[(k + 3) * LDB + m] = vb.w;
        }
    }
    __syncthreads();

    u64 acc2[8][4];                 // [u][pair p], pair covers v = 2p, 2p+1
#pragma unroll
    for (int u = 0; u < 8; u++)
#pragma unroll
        for (int p = 0; p < 4; p++) acc2[u][p] = 0ull;

    // ---- mainloop: 128 k-steps, 32 FFMA2 each ----
#pragma unroll 4
    for (int k = 0; k < DD; k++) {
        const float* arow = &As[k * LDAA + ty * 16];
        const float* brow = &Bs[k * LDB + tx * 8];
        ulonglong2 aa0 = *(const ulonglong2*)(arow);       // (a0,a0),(a1,a1)
        ulonglong2 aa1 = *(const ulonglong2*)(arow + 4);   // (a2,a2),(a3,a3)
        ulonglong2 aa2 = *(const ulonglong2*)(arow + 8);
        ulonglong2 aa3 = *(const ulonglong2*)(arow + 12);
        ulonglong2 bb0 = *(const ulonglong2*)(brow);       // (b0,b1),(b2,b3)
        ulonglong2 bb1 = *(const ulonglong2*)(brow + 4);   // (b4,b5),(b6,b7)
        u64 a2[8] = {aa0.x, aa0.y, aa1.x, aa1.y, aa2.x, aa2.y, aa3.x, aa3.y};
        u64 b2[4] = {bb0.x, bb0.y, bb1.x, bb1.y};
#pragma unroll
        for (int u = 0; u < 8; u++)
#pragma unroll
            for (int p = 0; p < 4; p++)
                acc2[u][p] = fma2(a2[u], b2[p], acc2[u][p]);
    }

    // ---- epilogue ----
    float maxd_l = 0.0f;            // dist >= 0 always
    float maxe_l = -3.0e38f;
    float mine_l = 3.0e38f;

#pragma unroll
    for (int u = 0; u < 8; u++) {
        const int i = i0 + ty * 8 + u;

        float accf[8];
#pragma unroll
        for (int p = 0; p < 4; p++) unpack2(accf[2 * p], accf[2 * p + 1], acc2[u][p]);

        float ns = 0.0f, s = 0.0f, pcnt = 0.0f;
        float dv[8];
#pragma unroll
        for (int v = 0; v < 8; v++) {
            const float mink = accf[v];
            const float theta = fmaxf(-mink, 1.0f + 1e-7f);
            // acosh(theta) = log(theta + sqrt(theta^2 - 1))
            const float ach = __logf(theta + __fsqrt_rn(fmaf(theta, theta, -1.0f)));
            const float dist = fminf(ach * ach, 50.0f);
            dv[v] = dist;
            maxd_l = fmaxf(maxd_l, dist);
            const float simi = fmaxf(__expf(-dist), 1e-15f);
            if ((amask >> (u * 8 + v)) & 1ull) {
                s += fmaxf(-dist, LOG_MIN);   // log(max(exp(-dist),1e-15))
                pcnt += 1.0f;
                maxe_l = fmaxf(maxe_l, mink); // edge_inner = mink * posf
                mine_l = fminf(mine_l, mink);
            } else {
                ns += simi;
                maxe_l = fmaxf(maxe_l, 0.0f); // posf==0 contributes 0
                mine_l = fminf(mine_l, 0.0f);
            }
        }
        float* drow = dist_out + (size_t)i * NN + j0 + tx * 8;
        *(float4*)drow = make_float4(dv[0], dv[1], dv[2], dv[3]);
        *(float4*)(drow + 4) = make_float4(dv[4], dv[5], dv[6], dv[7]);

        // reduce ns/s/p across the 16 tx-lanes (fixed xor-tree order)
#pragma unroll
        for (int o = 8; o >= 1; o >>= 1) {
            ns   += __shfl_xor_sync(0xFFFFFFFFu, ns,   o);
            s    += __shfl_xor_sync(0xFFFFFFFFu, s,    o);
            pcnt += __shfl_xor_sync(0xFFFFFFFFu, pcnt, o);
        }
        if (tx == 0) {  // deterministic: one writer per (col-block, row)
            g_neg[blockIdx.x * NN + i] = ns;
            g_S[blockIdx.x * NN + i]   = s;
            g_P[blockIdx.x * NN + i]   = pcnt;
        }
    }

    // warp-reduce min/max then atomics (exact ops => order-independent)
#pragma unroll
    for (int o = 16; o >= 1; o >>= 1) {
        maxd_l = fmaxf(maxd_l, __shfl_xor_sync(0xFFFFFFFFu, maxd_l, o));
        maxe_l = fmaxf(maxe_l, __shfl_xor_sync(0xFFFFFFFFu, maxe_l, o));
        mine_l = fminf(mine_l, __shfl_xor_sync(0xFFFFFFFFu, mine_l, o));
    }
    if ((tid & 31) == 0) {
        atomicMax(&g_maxd, fenc(maxd_l));
        atomicMax(&g_maxe, fenc(maxe_l));
        atomicMin(&g_mine, fenc(mine_l));
    }
}

// ---------------- per-row reduce -> loss (single block: deterministic) ----
__global__ void __launch_bounds__(1024) reduce_kernel() {
    __shared__ float sh[32];
    float acc = 0.0f;
#pragma unroll
    for (int r = 0; r < 4; r++) {
        const int i = r * 1024 + threadIdx.x;     // row 0..4095
        float ns = 0.0f, s = 0.0f, p = 0.0f;
#pragma unroll
        for (int cb = 0; cb < 32; cb++) {
            ns += g_neg[cb * NN + i];
            s  += g_S[cb * NN + i];
            p  += g_P[cb * NN + i];
        }
        acc += s - p * logf(ns);                  // sum_pos log(ratio), row i
    }
#pragma unroll
    for (int o = 16; o >= 1; o >>= 1)
        acc += __shfl_xor_sync(0xFFFFFFFFu, acc, o);
    const int wid = threadIdx.x >> 5;
    if ((threadIdx.x & 31) == 0) sh[wid] = acc;
    __syncthreads();
    if (threadIdx.x == 0) {
        float t = 0.0f;
#pragma unroll
        for (int w = 0; w < 32; w++) t += sh[w];
        g_loss = t;
    }
}

__global__ void finalize_kernel(float* out_scalars) {
    out_scalars[0] = -g_loss;
    out_scalars[1] = fdec(g_maxd);
    out_scalars[2] = fdec(g_maxe);
    out_scalars[3] = fdec(g_mine);
}

// ---------------- launch ----------------
extern "C" void kernel_launch(void* const* d_in, const int* in_sizes, int n_in,
                              void* d_out, int out_size) {
    const float* x = (const float*)d_in[0];
    const int* adj = (const int*)d_in[1];
    float* out = (float*)d_out;

    float* out_x       = out;
    float* out_dist    = out + (size_t)NN * DD;
    float* out_scalars = out_dist + (size_t)NN * NN;

    cudaFuncSetAttribute(dist_kernel, cudaFuncAttributeMaxDynamicSharedMemorySize,
                         SMEM_BYTES);

    cudaMemcpyAsync(out_x, x, (size_t)NN * DD * sizeof(float),
                    cudaMemcpyDeviceToDevice, 0);
    init_kernel<<<1, 1>>>();
    dist_kernel<<<dim3(32, 32), 256, SMEM_BYTES>>>(x, adj, out_dist);
    reduce_kernel<<<1, 1024>>>();
    finalize_kernel<<<1, 1>>>(out_scalars);
}

// round 7
// speedup vs baseline: 2.3061x; 2.3061x over previous
#include <cuda_runtime.h>
#include <cuda_bf16.h>
#include <cstdint>

typedef unsigned long long u64;

#define NN 4096
#define DD 128
#define LOG_MIN (-34.538776394910684f)   // log(1e-15)

#define TROW 272                  // smem tile row stride in bytes (136 bf16)
#define TILE_U4 2176              // uint4 per tile (128 rows * 17)
#define TILE_BYTES 34816
#define OFF_AHI 0
#define OFF_ALO 34816
#define OFF_BHI 69632
#define OFF_BLO 104448
#define SMEM_TOTAL 139264

// ---------------- device scratch (zero-init, no allocations) ----------------
__device__ uint4 g_tAhi[32 * TILE_U4];   // padded [row][136] bf16 tiles, k0 negated
__device__ uint4 g_tAlo[32 * TILE_U4];
__device__ uint4 g_tBhi[32 * TILE_U4];
__device__ uint4 g_tBlo[32 * TILE_U4];
__device__ float g_neg[NN * 128];        // [row][colblock32] partial negative_sum
__device__ float g_S[NN * 128];          // [row][colblock32] partial sum_pos(-dist)
__device__ float g_P[NN * 128];          // [row][colblock32] partial pos count
__device__ float g_blk[128];
__device__ unsigned g_cnt;
__device__ unsigned g_maxd, g_maxe, g_mine;

__device__ __forceinline__ unsigned fenc(float f) {
    unsigned u = __float_as_uint(f);
    return (u & 0x80000000u) ? ~u : (u | 0x80000000u);
}
__device__ __forceinline__ float fdec(unsigned u) {
    return (u & 0x80000000u) ? __uint_as_float(u ^ 0x80000000u)
                             : __uint_as_float(~u);
}
__device__ __forceinline__ uint32_t smem_u32(const void* p) {
    uint32_t a;
    asm("{ .reg .u64 t; cvta.to.shared.u64 t, %1; cvt.u32.u64 %0, t; }"
        : "=r"(a) : "l"(p));
    return a;
}
__device__ __forceinline__ float rsqrt_ap(float x) {
    float y; asm("rsqrt.approx.f32 %0, %1;" : "=f"(y) : "f"(x)); return y;
}
__device__ __forceinline__ void ldsm4(unsigned* r, uint32_t addr) {
    asm volatile("ldmatrix.sync.aligned.m8n8.x4.shared.b16 {%0,%1,%2,%3}, [%4];"
        : "=r"(r[0]), "=r"(r[1]), "=r"(r[2]), "=r"(r[3]) : "r"(addr));
}
__device__ __forceinline__ void mma16816(float* c, const unsigned* a, const unsigned* b) {
    asm volatile("mma.sync.aligned.m16n8k16.row.col.f32.bf16.bf16.f32 "
        "{%0,%1,%2,%3}, {%4,%5,%6,%7}, {%8,%9}, {%0,%1,%2,%3};"
        : "+f"(c[0]), "+f"(c[1]), "+f"(c[2]), "+f"(c[3])
        : "r"(a[0]), "r"(a[1]), "r"(a[2]), "r"(a[3]), "r"(b[0]), "r"(b[1]));
}

// ---------------- prep: x copy + padded bf16 hi/lo tile blobs ----------------
__global__ void __launch_bounds__(256) prep_kernel(const float* __restrict__ x,
                                                   float* __restrict__ out_x) {
    const int idx = blockIdx.x * 256 + threadIdx.x;   // 0..65535
    const int row = idx >> 4;                          // 0..4095
    const int kc = (idx & 15) << 3;                    // 0,8,...,120
    const float4* p = (const float4*)(x + (size_t)row * DD + kc);
    float4 v0 = p[0], v1 = p[1];
    float4* po = (float4*)(out_x + (size_t)row * DD + kc);
    po[0] = v0; po[1] = v1;                            // output x copy

    float vs[8] = {v0.x, v0.y, v0.z, v0.w, v1.x, v1.y, v1.z, v1.w};
    unsigned hh[8], ll[8];
#pragma unroll
    for (int e = 0; e < 8; e++) {
        __nv_bfloat16 h = __float2bfloat16(vs[e]);
        float hf = __bfloat162float(h);
        __nv_bfloat16 l = __float2bfloat16(vs[e] - hf);
        hh[e] = (unsigned)__bfloat16_as_ushort(h);
        ll[e] = (unsigned)__bfloat16_as_ushort(l);
    }
    uint4 uhB = make_uint4(hh[0] | (hh[1] << 16), hh[2] | (hh[3] << 16),
                           hh[4] | (hh[5] << 16), hh[6] | (hh[7] << 16));
    uint4 ulB = make_uint4(ll[0] | (ll[1] << 16), ll[2] | (ll[3] << 16),
                           ll[4] | (ll[5] << 16), ll[6] | (ll[7] << 16));
    uint4 uhA = uhB, ulA = ulB;
    if (kc == 0) {        // Minkowski sign on k=0: bf16 negate = sign-bit XOR
        uhA.x ^= 0x8000u;
        ulA.x ^= 0x8000u;
    }
    const int u4i = (row >> 7) * TILE_U4 + (row & 127) * 17 + (kc >> 3);
    g_tAhi[u4i] = uhA;
    g_tAlo[u4i] = ulA;
    g_tBhi[u4i] = uhB;
    g_tBlo[u4i] = ulB;

    if (idx == 0) {
        g_maxd = 0u;
        g_maxe = 0u;
        g_mine = 0xFFFFFFFFu;
        g_cnt = 0u;
    }
}

// ---------------- fused HMMA Gram + epilogue ----------------
extern __shared__ char smem[];

__global__ void __launch_bounds__(256, 1)
dist_kernel(const int* __restrict__ adj, float* __restrict__ dist_out) {
    const uint32_t sb = smem_u32(smem);
    const int tid = threadIdx.x;
    const int warp = tid >> 5, lane = tid & 31;
    const int wm = warp >> 2, wn = warp & 3;      // 2 x 4 warp grid
    const int g = lane >> 2, t = lane & 3;
    const int i0 = blockIdx.y * 128, j0 = blockIdx.x * 128;

    // ---- adjacency prefetch (drains under copies + MMA) ----
    u64 amask = 0ull;
#pragma unroll
    for (int mt = 0; mt < 4; mt++)
#pragma unroll
        for (int rh = 0; rh < 2; rh++) {
            const int i = i0 + wm * 64 + mt * 16 + rh * 8 + g;
            const int2* ap = (const int2*)(adj + (size_t)i * NN + j0 + wn * 32 + 2 * t);
#pragma unroll
            for (int nt = 0; nt < 4; nt++) {
                int2 a = __ldg(ap + nt * 4);
                const int bi = (mt * 2 + rh) * 8 + nt * 2;
                amask |= ((u64)(a.x != 0)) << bi;
                amask |= ((u64)(a.y != 0)) << (bi + 1);
            }
        }

    // ---- copy precomputed padded tiles into smem ----
    {
        const uint4* sAh = g_tAhi + blockIdx.y * TILE_U4;
        const uint4* sAl = g_tAlo + blockIdx.y * TILE_U4;
        const uint4* sBh = g_tBhi + blockIdx.x * TILE_U4;
        const uint4* sBl = g_tBlo + blockIdx.x * TILE_U4;
        uint4* dAh = (uint4*)(smem + OFF_AHI);
        uint4* dAl = (uint4*)(smem + OFF_ALO);
        uint4* dBh = (uint4*)(smem + OFF_BHI);
        uint4* dBl = (uint4*)(smem + OFF_BLO);
#pragma unroll
        for (int q = 0; q < 9; q++) {
            const int e = q * 256 + tid;
            if (e < TILE_U4) {
                dAh[e] = __ldg(sAh + e);
                dAl[e] = __ldg(sAl + e);
                dBh[e] = __ldg(sBh + e);
                dBl[e] = __ldg(sBl + e);
            }
        }
    }
    __syncthreads();

    float acc[4][4][4];
#pragma unroll
    for (int mt = 0; mt < 4; mt++)
#pragma unroll
        for (int nt = 0; nt < 4; nt++)
#pragma unroll
            for (int e = 0; e < 4; e++) acc[mt][nt][e] = 0.0f;

    // ldmatrix lane address components
    const uint32_t aLane = (uint32_t)((lane & 15) * TROW + (lane >> 4) * 16);
    const uint32_t bLane = (uint32_t)(((lane >> 4) * 8 + (lane & 7)) * TROW
                                      + ((lane >> 3) & 1) * 16);
    const uint32_t aRowBase = sb + (uint32_t)(wm * 64) * TROW + aLane;
    const uint32_t bRowBase = sb + (uint32_t)(wn * 32) * TROW + bLane;

    // ---- 3 precision passes: Ahi*Bhi + Ahi*Blo + Alo*Bhi ----
#pragma unroll
    for (int pass = 0; pass < 3; pass++) {
        const uint32_t aOff = (pass < 2) ? OFF_AHI : OFF_ALO;
        const uint32_t bOff = (pass == 1) ? OFF_BLO : OFF_BHI;
#pragma unroll 2
        for (int kk = 0; kk < 8; kk++) {
            unsigned aF[4][4], bF[4][2], bt[4];
#pragma unroll
            for (int mt = 0; mt < 4; mt++)
                ldsm4(aF[mt], aRowBase + aOff + (uint32_t)(mt * 16 * TROW) + kk * 32);
            ldsm4(bt, bRowBase + bOff + kk * 32);
            bF[0][0] = bt[0]; bF[0][1] = bt[1];
            bF[1][0] = bt[2]; bF[1][1] = bt[3];
            ldsm4(bt, bRowBase + bOff + (uint32_t)(16 * TROW) + kk * 32);
            bF[2][0] = bt[0]; bF[2][1] = bt[1];
            bF[3][0] = bt[2]; bF[3][1] = bt[3];
#pragma unroll
            for (int mt = 0; mt < 4; mt++)
#pragma unroll
                for (int nt = 0; nt < 4; nt++)
                    mma16816(acc[mt][nt], aF[mt], bF[nt]);
        }
    }

    // ---- epilogue ----
    float maxd = 0.0f, maxe = -3.0e38f, mine = 3.0e38f;
    const int jb = j0 + wn * 32 + 2 * t;

#pragma unroll
    for (int mt = 0; mt < 4; mt++)
#pragma unroll
        for (int rh = 0; rh < 2; rh++) {
            const int i = i0 + wm * 64 + mt * 16 + rh * 8 + g;
            float ns = 0.0f, s = 0.0f, pc = 0.0f;
            float* drow = dist_out + (size_t)i * NN + jb;
#pragma unroll
            for (int nt = 0; nt < 4; nt++) {
                float dv[2];
#pragma unroll
                for (int c = 0; c < 2; c++) {
                    float mink = acc[mt][nt][rh * 2 + c];
                    const int j = jb + nt * 8 + c;
                    if (j == i) mink = -1.0f;     // exact diagonal
                    const float theta = fmaxf(-mink, 1.0f + 1e-7f);
                    const float z = fmaf(theta, theta, -1.0f);
                    const float ach = __logf(fmaf(z, rsqrt_ap(z), theta));
                    const float dist = fminf(ach * ach, 50.0f);
                    dv[c] = dist;
                    maxd = fmaxf(maxd, dist);
                    const float simi = fmaxf(__expf(-dist), 1e-15f);
                    if ((amask >> ((mt * 2 + rh) * 8 + nt * 2 + c)) & 1ull) {
                        s += fmaxf(-dist, LOG_MIN);
                        pc += 1.0f;
                        maxe = fmaxf(maxe, mink);
                        mine = fminf(mine, mink);
                    } else {
                        ns += simi;
                        maxe = fmaxf(maxe, 0.0f);
                        mine = fminf(mine, 0.0f);
                    }
                }
                *(float2*)(drow + nt * 8) = make_float2(dv[0], dv[1]);
            }
            // reduce over the 4 quad lanes (same g, t=0..3), fixed xor order
            ns += __shfl_xor_sync(0xFFFFFFFFu, ns, 1);
            ns += __shfl_xor_sync(0xFFFFFFFFu, ns, 2);
            s  += __shfl_xor_sync(0xFFFFFFFFu, s, 1);
            s  += __shfl_xor_sync(0xFFFFFFFFu, s, 2);
            pc += __shfl_xor_sync(0xFFFFFFFFu, pc, 1);
            pc += __shfl_xor_sync(0xFFFFFFFFu, pc, 2);
            if (t == 0) {   // one writer per (row, 32-col block): deterministic
                const int cb = blockIdx.x * 4 + wn;
                g_neg[(size_t)i * 128 + cb] = ns;
                g_S[(size_t)i * 128 + cb]   = s;
                g_P[(size_t)i * 128 + cb]   = pc;
            }
        }

    // min/max: warp reduce then atomics (exact ops => order-independent)
#pragma unroll
    for (int o = 16; o >= 1; o >>= 1) {
        maxd = fmaxf(maxd, __shfl_xor_sync(0xFFFFFFFFu, maxd, o));
        maxe = fmaxf(maxe, __shfl_xor_sync(0xFFFFFFFFu, maxe, o));
        mine = fminf(mine, __shfl_xor_sync(0xFFFFFFFFu, mine, o));
    }
    if (lane == 0) {
        atomicMax(&g_maxd, fenc(maxd));
        atomicMax(&g_maxe, fenc(maxe));
        atomicMin(&g_mine, fenc(mine));
    }
}

// ---------------- two-stage reduce -> loss + scalars ----------------
__global__ void __launch_bounds__(256) reduce_kernel(float* out_scalars) {
    __shared__ float sh[32];
    const int tid = threadIdx.x;
    const int r = blockIdx.x * 32 + (tid >> 3);   // row
    const int l8 = tid & 7;
    float ns = 0.0f, s = 0.0f, p = 0.0f;
    const float4* pn = (const float4*)&g_neg[(size_t)r * 128 + l8 * 16];
    const float4* ps = (const float4*)&g_S[(size_t)r * 128 + l8 * 16];
    const float4* pp = (const float4*)&g_P[(size_t)r * 128 + l8 * 16];
#pragma unroll
    for (int q = 0; q < 4; q++) {
        float4 a = pn[q], b = ps[q], c = pp[q];
        ns += a.x + a.y + a.z + a.w;
        s  += b.x + b.y + b.z + b.w;
        p  += c.x + c.y + c.z + c.w;
    }
#pragma unroll
    for (int o = 4; o >= 1; o >>= 1) {
        ns += __shfl_xor_sync(0xFFFFFFFFu, ns, o);
        s  += __shfl_xor_sync(0xFFFFFFFFu, s, o);
        p  += __shfl_xor_sync(0xFFFFFFFFu, p, o);
    }
    if (l8 == 0) sh[tid >> 3] = s - p * logf(ns);   // row loss contribution
    __syncthreads();
    if (tid == 0) {
        float bsum = 0.0f;
#pragma unroll
        for (int k = 0; k < 32; k++) bsum += sh[k];
        g_blk[blockIdx.x] = bsum;
        __threadfence();
        const unsigned c = atomicAdd(&g_cnt, 1u);
        if (c == 127u) {                              // last block finalizes
            __threadfence();
            float tot = 0.0f;
            for (int k = 0; k < 128; k++) tot += g_blk[k];
            out_scalars[0] = -tot;
            out_scalars[1] = fdec(g_maxd);
            out_scalars[2] = fdec(g_maxe);
            out_scalars[3] = fdec(g_mine);
        }
    }
}

// ---------------- launch ----------------
extern "C" void kernel_launch(void* const* d_in, const int* in_sizes, int n_in,
                              void* d_out, int out_size) {
    const float* x = (const float*)d_in[0];
    const int* adj = (const int*)d_in[1];
    float* out = (float*)d_out;

    float* out_x       = out;
    float* out_dist    = out + (size_t)NN * DD;
    float* out_scalars = out_dist + (size_t)NN * NN;

    cudaFuncSetAttribute(dist_kernel, cudaFuncAttributeMaxDynamicSharedMemorySize,
                         SMEM_TOTAL);

    prep_kernel<<<256, 256>>>(x, out_x);
    dist_kernel<<<dim3(32, 32), 256, SMEM_TOTAL>>>(adj, out_dist);
    reduce_kernel<<<128, 256>>>(out_scalars);
}

// round 14
// speedup vs baseline: 2.8408x; 1.2318x over previous
#include <cuda_runtime.h>
#include <cuda_fp16.h>
#include <cstdint>

typedef unsigned long long u64;

#define NN 4096
#define DD 128
#define LOG_MIN (-34.538776394910684f)   // log(1e-15)

#define TROW 272                  // smem tile row stride in bytes (136 fp16)
#define TILE_U4 2176              // uint4 per tile (128 rows * 17)
#define OFF_A 0
#define OFF_B 34816
#define OFF_X0I 69632
#define OFF_X0J 70144
#define SMEM_TOTAL 70656

// ---------------- device scratch (no allocations) ----------------
__device__ uint4 g_tX[32 * TILE_U4];     // padded fp16 xs tiles (k=0 zeroed)
__device__ float g_x0[NN];
__device__ float g_neg[NN * 128];        // [row][colblock32] partial negative_sum
__device__ float g_S[NN * 128];          // [row][colblock32] partial sum_pos(-dist)
__device__ float g_P[NN * 128];          // [row][colblock32] partial pos count
__device__ float g_blk[128];
__device__ unsigned g_cnt;
__device__ unsigned g_maxd, g_maxe, g_mine;

__device__ __forceinline__ unsigned fenc(float f) {
    unsigned u = __float_as_uint(f);
    return (u & 0x80000000u) ? ~u : (u | 0x80000000u);
}
__device__ __forceinline__ float fdec(unsigned u) {
    return (u & 0x80000000u) ? __uint_as_float(u ^ 0x80000000u)
                             : __uint_as_float(~u);
}
__device__ __forceinline__ uint32_t smem_u32(const void* p) {
    uint32_t a;
    asm("{ .reg .u64 t; cvta.to.shared.u64 t, %1; cvt.u32.u64 %0, t; }"
        : "=r"(a) : "l"(p));
    return a;
}
__device__ __forceinline__ float rsqrt_ap(float x) {
    float y; asm("rsqrt.approx.f32 %0, %1;" : "=f"(y) : "f"(x)); return y;
}
__device__ __forceinline__ void cpasync16(uint32_t dst, const void* src) {
    asm volatile("cp.async.cg.shared.global [%0], [%1], 16;"
                 :: "r"(dst), "l"(src) : "memory");
}
__device__ __forceinline__ void ldsm4(unsigned* r, uint32_t addr) {
    asm volatile("ldmatrix.sync.aligned.m8n8.x4.shared.b16 {%0,%1,%2,%3}, [%4];"
        : "=r"(r[0]), "=r"(r[1]), "=r"(r[2]), "=r"(r[3]) : "r"(addr));
}
__device__ __forceinline__ void mma16816(float* c, const unsigned* a, const unsigned* b) {
    asm volatile("mma.sync.aligned.m16n8k16.row.col.f32.f16.f16.f32 "
        "{%0,%1,%2,%3}, {%4,%5,%6,%7}, {%8,%9}, {%0,%1,%2,%3};"
        : "+f"(c[0]), "+f"(c[1]), "+f"(c[2]), "+f"(c[3])
        : "r"(a[0]), "r"(a[1]), "r"(a[2]), "r"(a[3]), "r"(b[0]), "r"(b[1]));
}

// ---------------- prep: x copy + x0 + fp16 xs tile blob ----------------
__global__ void __launch_bounds__(256) prep_kernel(const float* __restrict__ x,
                                                   float* __restrict__ out_x) {
    const int idx = blockIdx.x * 256 + threadIdx.x;   // 0..65535
    const int row = idx >> 4;                          // 0..4095
    const int kc = (idx & 15) << 3;                    // 0,8,...,120
    const float4* p = (const float4*)(x + (size_t)row * DD + kc);
    float4 v0 = p[0], v1 = p[1];
    float4* po = (float4*)(out_x + (size_t)row * DD + kc);
    po[0] = v0; po[1] = v1;                            // output x copy

    if (kc == 0) {
        g_x0[row] = v0.x;      // time component, exact fp32
        v0.x = 0.0f;           // exclude from fp16 Gram
    }
    float vs[8] = {v0.x, v0.y, v0.z, v0.w, v1.x, v1.y, v1.z, v1.w};
    unsigned hh[8];
#pragma unroll
    for (int e = 0; e < 8; e++)
        hh[e] = (unsigned)__half_as_ushort(__float2half_rn(vs[e]));
    uint4 uh = make_uint4(hh[0] | (hh[1] << 16), hh[2] | (hh[3] << 16),
                          hh[4] | (hh[5] << 16), hh[6] | (hh[7] << 16));
    g_tX[(row >> 7) * TILE_U4 + (row & 127) * 17 + (kc >> 3)] = uh;

    if (idx == 0) {
        g_maxd = 0u;
        g_maxe = 0u;
        g_mine = 0xFFFFFFFFu;
        g_cnt = 0u;
    }
}

// ---------------- fused HMMA Gram + epilogue ----------------
extern __shared__ char smem[];

__global__ void __launch_bounds__(256, 2)
dist_kernel(const int* __restrict__ adj, float* __restrict__ dist_out) {
    const uint32_t sb = smem_u32(smem);
    const int tid = threadIdx.x;
    const int warp = tid >> 5, lane = tid & 31;
    const int wm = warp >> 2, wn = warp & 3;      // 2 x 4 warp grid
    const int g = lane >> 2, t = lane & 3;
    const int i0 = blockIdx.y * 128, j0 = blockIdx.x * 128;

    // ---- async copy of precomputed fp16 tiles + x0 slices into smem ----
    {
        const uint4* sA = g_tX + blockIdx.y * TILE_U4;
        const uint4* sB = g_tX + blockIdx.x * TILE_U4;
#pragma unroll
        for (int q = 0; q < 9; q++) {
            const int e = q * 256 + tid;
            if (e < TILE_U4) {
                cpasync16(sb + OFF_A + e * 16, sA + e);
                cpasync16(sb + OFF_B + e * 16, sB + e);
            }
        }
        if (tid < 128)
            *(float*)(smem + OFF_X0I + tid * 4) = __ldg(g_x0 + i0 + tid);
        else
            *(float*)(smem + OFF_X0J + (tid - 128) * 4) = __ldg(g_x0 + j0 + tid - 128);
        asm volatile("cp.async.commit_group;" ::: "memory");
    }

    // ---- adjacency prefetch (overlaps cp.async drain) ----
    u64 amask = 0ull;
#pragma unroll
    for (int mt = 0; mt < 4; mt++)
#pragma unroll
        for (int rh = 0; rh < 2; rh++) {
            const int i = i0 + wm * 64 + mt * 16 + rh * 8 + g;
            const int2* ap = (const int2*)(adj + (size_t)i * NN + j0 + wn * 32 + 2 * t);
#pragma unroll
            for (int nt = 0; nt < 4; nt++) {
                int2 a = __ldg(ap + nt * 4);
                const int bi = (mt * 2 + rh) * 8 + nt * 2;
                amask |= ((u64)(a.x != 0)) << bi;
                amask |= ((u64)(a.y != 0)) << (bi + 1);
            }
        }

    asm volatile("cp.async.wait_group 0;" ::: "memory");
    __syncthreads();

    float acc[4][4][4];
#pragma unroll
    for (int mt = 0; mt < 4; mt++)
#pragma unroll
        for (int nt = 0; nt < 4; nt++)
#pragma unroll
            for (int e = 0; e < 4; e++) acc[mt][nt][e] = 0.0f;

    // ldmatrix lane address components
    const uint32_t aLane = (uint32_t)((lane & 15) * TROW + (lane >> 4) * 16);
    const uint32_t bLane = (uint32_t)(((lane >> 4) * 8 + (lane & 7)) * TROW
                                      + ((lane >> 3) & 1) * 16);
    const uint32_t aRowBase = sb + OFF_A + (uint32_t)(wm * 64) * TROW + aLane;
    const uint32_t bRowBase = sb + OFF_B + (uint32_t)(wn * 32) * TROW + bLane;

    // ---- single fp16 pass: acc = xs_i . xs_j ----
#pragma unroll
    for (int kk = 0; kk < 8; kk++) {
        unsigned aF[4][4], bF[4][2], bt[4];
#pragma unroll
        for (int mt = 0; mt < 4; mt++)
            ldsm4(aF[mt], aRowBase + (uint32_t)(mt * 16 * TROW) + kk * 32);
        ldsm4(bt, bRowBase + kk * 32);
        bF[0][0] = bt[0]; bF[0][1] = bt[1];
        bF[1][0] = bt[2]; bF[1][1] = bt[3];
        ldsm4(bt, bRowBase + (uint32_t)(16 * TROW) + kk * 32);
        bF[2][0] = bt[0]; bF[2][1] = bt[1];
        bF[3][0] = bt[2]; bF[3][1] = bt[3];
#pragma unroll
        for (int mt = 0; mt < 4; mt++)
#pragma unroll
            for (int nt = 0; nt < 4; nt++)
                mma16816(acc[mt][nt], aF[mt], bF[nt]);
    }

    // ---- epilogue: mink = acc - x0_i*x0_j (fp32 exact) ----
    float maxd = 0.0f, maxe = -3.0e38f, mine = 3.0e38f;
    const int jb = j0 + wn * 32 + 2 * t;

    float x0j[8];
#pragma unroll
    for (int nt = 0; nt < 4; nt++) {
        x0j[nt * 2]     = *(float*)(smem + OFF_X0J + (wn * 32 + nt * 8 + 2 * t) * 4);
        x0j[nt * 2 + 1] = *(float*)(smem + OFF_X0J + (wn * 32 + nt * 8 + 2 * t + 1) * 4);
    }

#pragma unroll
    for (int mt = 0; mt < 4; mt++)
#pragma unroll
        for (int rh = 0; rh < 2; rh++) {
            const int il = wm * 64 + mt * 16 + rh * 8 + g;
            const int i = i0 + il;
            const float x0i = *(float*)(smem + OFF_X0I + il * 4);
            float ns = 0.0f, s = 0.0f, pc = 0.0f;
            float* drow = dist_out + (size_t)i * NN + jb;
#pragma unroll
            for (int nt = 0; nt < 4; nt++) {
                float dv[2];
#pragma unroll
                for (int c = 0; c < 2; c++) {
                    float mink = fmaf(-x0i, x0j[nt * 2 + c], acc[mt][nt][rh * 2 + c]);
                    const int j = jb + nt * 8 + c;
                    if (j == i) mink = -1.0f;     // exact diagonal
                    const float theta = fmaxf(-mink, 1.0f + 1e-7f);
                    const float z = fmaf(theta, theta, -1.0f);
                    const float ach = __logf(fmaf(z, rsqrt_ap(z), theta));
                    const float dist = fminf(ach * ach, 50.0f);
                    dv[c] = dist;
                    maxd = fmaxf(maxd, dist);
                    const float simi = fmaxf(__expf(-dist), 1e-15f);
                    if ((amask >> ((mt * 2 + rh) * 8 + nt * 2 + c)) & 1ull) {
                        s += fmaxf(-dist, LOG_MIN);
                        pc += 1.0f;
                        maxe = fmaxf(maxe, mink);
                        mine = fminf(mine, mink);
                    } else {
                        ns += simi;
                        maxe = fmaxf(maxe, 0.0f);
                        mine = fminf(mine, 0.0f);
                    }
                }
                *(float2*)(drow + nt * 8) = make_float2(dv[0], dv[1]);
            }
            // reduce over the 4 quad lanes (same g, t=0..3), fixed xor order
            ns += __shfl_xor_sync(0xFFFFFFFFu, ns, 1);
            ns += __shfl_xor_sync(0xFFFFFFFFu, ns, 2);
            s  += __shfl_xor_sync(0xFFFFFFFFu, s, 1);
            s  += __shfl_xor_sync(0xFFFFFFFFu, s, 2);
            pc += __shfl_xor_sync(0xFFFFFFFFu, pc, 1);
            pc += __shfl_xor_sync(0xFFFFFFFFu, pc, 2);
            if (t == 0) {   // one writer per (row, 32-col block): deterministic
                const int cb = blockIdx.x * 4 + wn;
                g_neg[(size_t)i * 128 + cb] = ns;
                g_S[(size_t)i * 128 + cb]   = s;
                g_P[(size_t)i * 128 + cb]   = pc;
            }
        }

    // min/max: warp reduce then atomics (exact ops => order-independent)
#pragma unroll
    for (int o = 16; o >= 1; o >>= 1) {
        maxd = fmaxf(maxd, __shfl_xor_sync(0xFFFFFFFFu, maxd, o));
        maxe = fmaxf(maxe, __shfl_xor_sync(0xFFFFFFFFu, maxe, o));
        mine = fminf(mine, __shfl_xor_sync(0xFFFFFFFFu, mine, o));
    }
    if (lane == 0) {
        atomicMax(&g_maxd, fenc(maxd));
        atomicMax(&g_maxe, fenc(maxe));
        atomicMin(&g_mine, fenc(mine));
    }
}

// ---------------- two-stage reduce -> loss + scalars ----------------
__global__ void __launch_bounds__(256) reduce_kernel(float* out_scalars) {
    __shared__ float sh[32];
    const int tid = threadIdx.x;
    const int r = blockIdx.x * 32 + (tid >> 3);   // row
    const int l8 = tid & 7;
    float ns = 0.0f, s = 0.0f, p = 0.0f;
    const float4* pn = (const float4*)&g_neg[(size_t)r * 128 + l8 * 16];
    const float4* ps = (const float4*)&g_S[(size_t)r * 128 + l8 * 16];
    const float4* pp = (const float4*)&g_P[(size_t)r * 128 + l8 * 16];
#pragma unroll
    for (int q = 0; q < 4; q++) {
        float4 a = pn[q], b = ps[q], c = pp[q];
        ns += a.x + a.y + a.z + a.w;
        s  += b.x + b.y + b.z + b.w;
        p  += c.x + c.y + c.z + c.w;
    }
#pragma unroll
    for (int o = 4; o >= 1; o >>= 1) {
        ns += __shfl_xor_sync(0xFFFFFFFFu, ns, o);
        s  += __shfl_xor_sync(0xFFFFFFFFu, s, o);
        p  += __shfl_xor_sync(0xFFFFFFFFu, p, o);
    }
    if (l8 == 0) sh[tid >> 3] = s - p * logf(ns);   // row loss contribution
    __syncthreads();
    if (tid == 0) {
        float bsum = 0.0f;
#pragma unroll
        for (int k = 0; k < 32; k++) bsum += sh[k];
        g_blk[blockIdx.x] = bsum;
        __threadfence();
        const unsigned c = atomicAdd(&g_cnt, 1u);
        if (c == 127u) {                              // last block finalizes
            __threadfence();
            float tot = 0.0f;
            for (int k = 0; k < 128; k++) tot += g_blk[k];
            out_scalars[0] = -tot;
            out_scalars[1] = fdec(g_maxd);
            out_scalars[2] = fdec(g_maxe);
            out_scalars[3] = fdec(g_mine);
        }
    }
}

// ---------------- launch ----------------
extern "C" void kernel_launch(void* const* d_in, const int* in_sizes, int n_in,
                              void* d_out, int out_size) {
    const float* x = (const float*)d_in[0];
    const int* adj = (const int*)d_in[1];
    float* out = (float*)d_out;

    float* out_x       = out;
    float* out_dist    = out + (size_t)NN * DD;
    float* out_scalars = out_dist + (size_t)NN * NN;

    cudaFuncSetAttribute(dist_kernel, cudaFuncAttributeMaxDynamicSharedMemorySize,
                         SMEM_TOTAL);

    prep_kernel<<<256, 256>>>(x, out_x);
    dist_kernel<<<dim3(32, 32), 256, SMEM_TOTAL>>>(adj, out_dist);
    reduce_kernel<<<128, 256>>>(out_scalars);
}